// round 10
// baseline (speedup 1.0000x reference)
#include <cuda_runtime.h>

// ---------------- problem constants (fixed shapes) ----------------
#define B_    4
#define D_    118
#define H_    32              // == warp size: lane <-> h
#define W_    88
#define C_    80
#define NX_   360
#define NY_   360
#define XY_   (NX_ * NY_)     // 129600
#define WPB   44              // w-columns per block (2 blocks per (b,d) slab)
#define TASKS (WPB * (C_ / 4))// 880 float4 tasks per block
#define ROW4  (W_ * C_ / 4)   // 1760 float4 per (b,d,h) row

// ---------------- kernel 1: zero all of d_out (poisoned 0xAA) --------------
__global__ void zero_out_kernel(float4* __restrict__ o) {
    size_t i = (size_t)blockIdx.x * blockDim.x + threadIdx.x;
    o[i] = make_float4(0.f, 0.f, 0.f, 0.f);   // grid sized exactly: no guard
}

// ---------------- kernel 2: slab-per-block aggregated scatter --------------
// Structural fact (validated R5-R9): combine[0][1] == combine[1][1] == 0
// exactly in fp32, so gx,gy are identical across the 32 h's of a (b,d,w)
// column; only the cz==0 test varies with h. Phase 1: 8 warps compute the 44
// column masks/voxels (lane == h) with ballot + uniformity fallback. Phase 2:
// x rows for fixed (b,d,h) are contiguous across w, so the block streams a
// contiguous 14KB run per h with ALL 32 lanes active (vs 20/32 in R7), each
// thread carrying 4 independent accumulator chains; loads predicated on the
// column mask bit so rejected columns/h's cost no traffic. One aggregated
// commit per (column, channel-group) straight into the (B,C,X,Y) layout.
__global__ void __launch_bounds__(256)
scatter_kernel(const float* __restrict__ x, const float* __restrict__ frustum,
               float* __restrict__ out,
               const float* __restrict__ rots,
               const float* __restrict__ trans,
               const float* __restrict__ intrins) {
    __shared__ float s_cmb[9];
    __shared__ float s_tr[3];
    __shared__ unsigned s_mask[WPB];
    __shared__ int s_cx[WPB], s_cy[WPB];

    int tid  = threadIdx.x;
    int lane = tid & 31;                 // lane == h in phase 1
    int wid  = tid >> 5;
    int blk  = blockIdx.x;               // ((b*D + d)*2 + wh)
    int wh   = blk & 1;
    int t    = blk >> 1;
    int d    = t % D_;
    int b    = t / D_;

    // --- per-block setup: combine = rots[b] @ inv(intrins[b]) (dbl adjugate)
    if (tid == 0) {
        const float* K = intrins + b * 9;
        double a00 = K[0], a01 = K[1], a02 = K[2];
        double a10 = K[3], a11 = K[4], a12 = K[5];
        double a20 = K[6], a21 = K[7], a22 = K[8];
        double det = a00 * (a11 * a22 - a12 * a21)
                   - a01 * (a10 * a22 - a12 * a20)
                   + a02 * (a10 * a21 - a11 * a20);
        double id = 1.0 / det;
        float inv[9];
        inv[0] = (float)(( a11 * a22 - a12 * a21) * id);
        inv[1] = (float)((-(a01 * a22 - a02 * a21)) * id);
        inv[2] = (float)(( a01 * a12 - a02 * a11) * id);
        inv[3] = (float)((-(a10 * a22 - a12 * a20)) * id);
        inv[4] = (float)(( a00 * a22 - a02 * a20) * id);
        inv[5] = (float)((-(a00 * a12 - a02 * a10)) * id);
        inv[6] = (float)(( a10 * a21 - a11 * a20) * id);
        inv[7] = (float)((-(a00 * a21 - a01 * a20)) * id);
        inv[8] = (float)(( a00 * a11 - a01 * a10) * id);
        const float* R = rots + b * 9;
        #pragma unroll
        for (int i = 0; i < 3; i++)
            #pragma unroll
            for (int j = 0; j < 3; j++)
                s_cmb[i * 3 + j] = R[i * 3 + 0] * inv[0 * 3 + j]
                                 + R[i * 3 + 1] * inv[1 * 3 + j]
                                 + R[i * 3 + 2] * inv[2 * 3 + j];
        s_tr[0] = trans[b * 3 + 0];
        s_tr[1] = trans[b * 3 + 1];
        s_tr[2] = trans[b * 3 + 2];
    }
    __syncthreads();

    // --------------- phase 1: masks + voxel for 44 columns ------------------
    for (int wl = wid; wl < WPB; wl += 8) {
        int w = wh * WPB + wl;

        // frustum (D,H,W,3): [...,0]=u (w only), [...,1]=v (h), [...,2]=depth
        const float* fr = frustum + ((size_t)(d * H_ + lane) * W_ + w) * 3;
        float fu = fr[0];                // uniform across lanes
        float fv = fr[1];                // per-lane (h)
        float fd = fr[2];                // uniform across lanes
        float p0 = fu * fd, p1 = fv * fd, p2 = fd;

        float gx = s_cmb[0] * p0 + s_cmb[1] * p1 + s_cmb[2] * p2 + s_tr[0];
        float gy = s_cmb[3] * p0 + s_cmb[4] * p1 + s_cmb[5] * p2 + s_tr[1];
        float gz = s_cmb[6] * p0 + s_cmb[7] * p1 + s_cmb[8] * p2 + s_tr[2];

        // matches ((geom - BX_LO)/DX).astype(int32): trunc toward zero,
        // incl. the (-1,0)->0 "kept" quirk of the reference
        int cx = (int)((gx + 54.0f) / 0.3f);
        int cy = (int)((gy + 54.0f) / 0.3f);
        int cz = (int)((gz + 10.0f) / 20.0f);

        bool pass = (unsigned)cx < (unsigned)NX_ && (unsigned)cy < (unsigned)NY_
                    && cz == 0;
        unsigned mask = __ballot_sync(0xFFFFFFFFu, pass);

        if (mask == 0u) {
            if (lane == 0) s_mask[wl] = 0u;
            continue;
        }
        int src = __ffs(mask) - 1;
        int cx0 = __shfl_sync(0xFFFFFFFFu, cx, src);
        int cy0 = __shfl_sync(0xFFFFFFFFu, cy, src);
        bool uni = __all_sync(0xFFFFFFFFu, !pass || (cx == cx0 && cy == cy0));

        if (uni) {
            if (lane == 0) { s_mask[wl] = mask; s_cx[wl] = cx0; s_cy[wl] = cy0; }
        } else {
            // exact fallback (never expected): per-h scalar scatter now
            if (lane == 0) s_mask[wl] = 0u;
            size_t xbase = ((size_t)((b * D_ + d) * H_) * W_ + w) * (size_t)C_;
            for (int h = 0; h < H_; h++) {
                if (!((mask >> h) & 1u)) continue;
                int cxh = __shfl_sync(0xFFFFFFFFu, cx, h);
                int cyh = __shfl_sync(0xFFFFFFFFu, cy, h);
                size_t q = (size_t)cxh * NY_ + cyh;
                const float* xr = x + xbase + (size_t)h * (W_ * C_);
                for (int c = lane; c < C_; c += 32)
                    atomicAdd(out + ((size_t)b * C_ + c) * XY_ + q, xr[c]);
            }
        }
    }
    __syncthreads();

    // --------------- phase 2: fully-coalesced accumulate --------------------
    // task i = tid + k*256 -> (w-local = i/20, channel-group = i%20)
    unsigned m0, m1, m2, m3;
    int w0 = (tid          ) / 20;
    int w1 = (tid + 256    ) / 20;
    int w2 = (tid + 512    ) / 20;
    int w3 = (tid + 768    ) / 20;      // valid only when tid < 112
    bool ok3 = (tid + 768) < TASKS;
    m0 = s_mask[w0];
    m1 = s_mask[w1];
    m2 = s_mask[w2];
    m3 = ok3 ? s_mask[w3] : 0u;

    const float4* xrow = reinterpret_cast<const float4*>(x)
                       + (size_t)(b * D_ + d) * (H_ * ROW4) + wh * TASKS;

    float4 a0 = make_float4(0.f, 0.f, 0.f, 0.f);
    float4 a1 = a0, a2 = a0, a3 = a0;

    #pragma unroll 8
    for (int h = 0; h < H_; h++) {
        const float4* r = xrow + (size_t)h * ROW4;
        if ((m0 >> h) & 1u) { float4 v = __ldcs(r + tid);
            a0.x += v.x; a0.y += v.y; a0.z += v.z; a0.w += v.w; }
        if ((m1 >> h) & 1u) { float4 v = __ldcs(r + tid + 256);
            a1.x += v.x; a1.y += v.y; a1.z += v.z; a1.w += v.w; }
        if ((m2 >> h) & 1u) { float4 v = __ldcs(r + tid + 512);
            a2.x += v.x; a2.y += v.y; a2.z += v.z; a2.w += v.w; }
        if ((m3 >> h) & 1u) { float4 v = __ldcs(r + tid + 768);
            a3.x += v.x; a3.y += v.y; a3.z += v.z; a3.w += v.w; }
    }

    // --------------- commit: 4 scalar atomics per live task -----------------
    #pragma unroll
    for (int k = 0; k < 4; k++) {
        unsigned m  = (k == 0) ? m0 : (k == 1) ? m1 : (k == 2) ? m2 : m3;
        if (m == 0u) continue;
        int i  = tid + k * 256;
        int wl = (k == 0) ? w0 : (k == 1) ? w1 : (k == 2) ? w2 : w3;
        int g  = i - wl * 20;
        float4 a = (k == 0) ? a0 : (k == 1) ? a1 : (k == 2) ? a2 : a3;
        size_t q  = (size_t)s_cx[wl] * NY_ + s_cy[wl];
        float* op = out + ((size_t)b * C_ + 4 * g) * XY_ + q;
        atomicAdd(op,                   a.x);
        atomicAdd(op + (size_t)XY_,     a.y);
        atomicAdd(op + 2 * (size_t)XY_, a.z);
        atomicAdd(op + 3 * (size_t)XY_, a.w);
    }
}

// ---------------- launch ----------------------------------------------------
extern "C" void kernel_launch(void* const* d_in, const int* in_sizes, int n_in,
                              void* d_out, int out_size) {
    const float* x       = (const float*)d_in[0];
    const float* rots    = (const float*)d_in[1];
    const float* trans   = (const float*)d_in[2];
    const float* intrins = (const float*)d_in[3];
    const float* frustum = (const float*)d_in[4];
    float* out = (float*)d_out;

    // 41,472,000 floats = 10,368,000 float4 = 40500 * 256 exactly
    zero_out_kernel<<<40500, 256>>>(reinterpret_cast<float4*>(out));

    // one block per (b, d, w-half): 4*118*2 = 944 blocks
    scatter_kernel<<<B_ * D_ * 2, 256>>>(x, frustum, out, rots, trans, intrins);
}

// round 11
// speedup vs baseline: 1.1543x; 1.1543x over previous
#include <cuda_runtime.h>

// ---------------- problem constants (fixed shapes) ----------------
#define B_    4
#define D_    118
#define H_    32              // == warp size: lane <-> h
#define W_    88
#define C_    80
#define NX_   360
#define NY_   360
#define XY_   (NX_ * NY_)     // 129600
#define NCOLB (D_ * W_)       // 10,384 columns per batch (divisible by 4)
#define NCOL  (B_ * NCOLB)    // 41,536 ray columns

// ---------------- kernel 1: zero all of d_out (poisoned 0xAA) --------------
__global__ void zero_out_kernel(float4* __restrict__ o) {
    unsigned i = blockIdx.x * blockDim.x + threadIdx.x;
    o[i] = make_float4(0.f, 0.f, 0.f, 0.f);   // grid sized exactly: no guard
}

// ---------------- kernel 2: warp-per-ray-column aggregated scatter ---------
// Structural fact (validated R5-R10): combine[0][1] == combine[1][1] == 0
// exactly in fp32, so gx,gy are identical across the 32 h's of a (b,d,w)
// column; only the cz==0 test varies with h. One warp aggregates a whole
// column in registers (warp-uniform mask -> scalar branch skips failing h's)
// and commits ONE feature vector with scalar atomics straight into the final
// (B,C,X,Y) layout. Uniformity check + exact per-h fallback guard the
// assumption.
//
// R11 change vs R7 (the 105.4us best): 128-thread blocks so occupancy
// quantizes at 4-warp granularity (11-12 blocks/SM = 44-48 warps vs 40), and
// all addressing in 32-bit (max index 106M < 2^32) to shave 64-bit IMAD reg
// pairs. Inner loop byte-identical to R7. NCOLB % 4 == 0 keeps b uniform per
// block for the thread-0 smem setup.
__global__ void __launch_bounds__(128)
scatter_kernel(const float* __restrict__ x, const float* __restrict__ frustum,
               float* __restrict__ out,
               const float* __restrict__ rots,
               const float* __restrict__ trans,
               const float* __restrict__ intrins) {
    __shared__ float s_cmb[9];
    __shared__ float s_tr[3];

    unsigned tid  = threadIdx.x;
    unsigned lane = tid & 31u;                    // lane == h
    unsigned col  = blockIdx.x * 4u + (tid >> 5); // one column per warp
    unsigned w = col % W_;
    unsigned t = col / W_;
    unsigned d = t % D_;
    unsigned b = t / D_;                          // uniform across the block

    // --- per-block setup: combine = rots[b] @ inv(intrins[b]) (dbl adjugate)
    if (tid == 0) {
        const float* K = intrins + b * 9;
        double a00 = K[0], a01 = K[1], a02 = K[2];
        double a10 = K[3], a11 = K[4], a12 = K[5];
        double a20 = K[6], a21 = K[7], a22 = K[8];
        double det = a00 * (a11 * a22 - a12 * a21)
                   - a01 * (a10 * a22 - a12 * a20)
                   + a02 * (a10 * a21 - a11 * a20);
        double id = 1.0 / det;
        float inv[9];
        inv[0] = (float)(( a11 * a22 - a12 * a21) * id);
        inv[1] = (float)((-(a01 * a22 - a02 * a21)) * id);
        inv[2] = (float)(( a01 * a12 - a02 * a11) * id);
        inv[3] = (float)((-(a10 * a22 - a12 * a20)) * id);
        inv[4] = (float)(( a00 * a22 - a02 * a20) * id);
        inv[5] = (float)((-(a00 * a12 - a02 * a10)) * id);
        inv[6] = (float)(( a10 * a21 - a11 * a20) * id);
        inv[7] = (float)((-(a00 * a21 - a01 * a20)) * id);
        inv[8] = (float)(( a00 * a11 - a01 * a10) * id);
        const float* R = rots + b * 9;
        #pragma unroll
        for (int i = 0; i < 3; i++)
            #pragma unroll
            for (int j = 0; j < 3; j++)
                s_cmb[i * 3 + j] = R[i * 3 + 0] * inv[0 * 3 + j]
                                 + R[i * 3 + 1] * inv[1 * 3 + j]
                                 + R[i * 3 + 2] * inv[2 * 3 + j];
        s_tr[0] = trans[b * 3 + 0];
        s_tr[1] = trans[b * 3 + 1];
        s_tr[2] = trans[b * 3 + 2];
    }
    __syncthreads();

    // frustum (D,H,W,3): [...,0]=u (w only), [...,1]=v (h only), [...,2]=depth
    const float* fr = frustum + ((d * H_ + lane) * W_ + w) * 3u;
    float fu = fr[0];     // uniform across lanes
    float fv = fr[1];     // per-lane (h)
    float fd = fr[2];     // uniform across lanes
    float p0 = fu * fd, p1 = fv * fd, p2 = fd;

    float gx = s_cmb[0] * p0 + s_cmb[1] * p1 + s_cmb[2] * p2 + s_tr[0];
    float gy = s_cmb[3] * p0 + s_cmb[4] * p1 + s_cmb[5] * p2 + s_tr[1];
    float gz = s_cmb[6] * p0 + s_cmb[7] * p1 + s_cmb[8] * p2 + s_tr[2];

    // matches ((geom - BX_LO)/DX).astype(int32): trunc toward zero,
    // incl. the (-1,0)->0 "kept" quirk of the reference
    int cx = (int)((gx + 54.0f) / 0.3f);
    int cy = (int)((gy + 54.0f) / 0.3f);
    int cz = (int)((gz + 10.0f) / 20.0f);

    bool pass = (unsigned)cx < (unsigned)NX_ && (unsigned)cy < (unsigned)NY_
                && cz == 0;
    unsigned mask = __ballot_sync(0xFFFFFFFFu, pass);
    if (mask == 0u) return;                  // whole column rejected: skip x

    int src = __ffs(mask) - 1;
    int cx0 = __shfl_sync(0xFFFFFFFFu, cx, src);
    int cy0 = __shfl_sync(0xFFFFFFFFu, cy, src);
    bool uni = __all_sync(0xFFFFFFFFu, !pass || (cx == cx0 && cy == cy0));

    unsigned xbase = (((b * D_ + d) * H_) * W_ + w) * (unsigned)C_;   // h = 0

    if (uni) {
        // lanes 0..19: accumulate one float4 channel group over passing h's
        // (warp-uniform mask -> scalar branch skips failing h's entirely)
        if (lane < C_ / 4) {
            const float* xp = x + xbase + 4u * lane;
            float4 acc = make_float4(0.f, 0.f, 0.f, 0.f);
            #pragma unroll
            for (unsigned h = 0; h < H_; h++) {
                if ((mask >> h) & 1u) {
                    float4 v = __ldcs(reinterpret_cast<const float4*>(
                        xp + h * (unsigned)(W_ * C_)));
                    acc.x += v.x; acc.y += v.y; acc.z += v.z; acc.w += v.w;
                }
            }
            unsigned q  = (unsigned)cx0 * NY_ + (unsigned)cy0;
            float* op = out + (b * C_ + 4u * lane) * (unsigned)XY_ + q;
            atomicAdd(op,            acc.x);
            atomicAdd(op + XY_,      acc.y);
            atomicAdd(op + 2 * XY_,  acc.z);
            atomicAdd(op + 3 * XY_,  acc.w);
        }
    } else {
        // exact fallback (never expected): per-h scalar scatter
        for (unsigned h = 0; h < H_; h++) {
            if (!((mask >> h) & 1u)) continue;
            int cxh = __shfl_sync(0xFFFFFFFFu, cx, h);
            int cyh = __shfl_sync(0xFFFFFFFFu, cy, h);
            unsigned q = (unsigned)cxh * NY_ + (unsigned)cyh;
            const float* xr = x + xbase + h * (unsigned)(W_ * C_);
            for (unsigned c = lane; c < C_; c += 32)
                atomicAdd(out + (b * C_ + c) * (unsigned)XY_ + q, xr[c]);
        }
    }
}

// ---------------- launch ----------------------------------------------------
extern "C" void kernel_launch(void* const* d_in, const int* in_sizes, int n_in,
                              void* d_out, int out_size) {
    const float* x       = (const float*)d_in[0];
    const float* rots    = (const float*)d_in[1];
    const float* trans   = (const float*)d_in[2];
    const float* intrins = (const float*)d_in[3];
    const float* frustum = (const float*)d_in[4];
    float* out = (float*)d_out;

    // 41,472,000 floats = 10,368,000 float4 = 40500 * 256 exactly
    zero_out_kernel<<<40500, 256>>>(reinterpret_cast<float4*>(out));

    // one warp per (b,d,w) column: 41536 warps, 4 per 128-thread block
    scatter_kernel<<<NCOL / 4, 128>>>(x, frustum, out, rots, trans, intrins);
}

// round 12
// speedup vs baseline: 1.2315x; 1.0669x over previous
#include <cuda_runtime.h>

// ---------------- problem constants (fixed shapes) ----------------
#define B_    4
#define D_    118
#define H_    32              // == warp size: lane <-> h
#define W_    88
#define C_    80
#define NX_   360
#define NY_   360
#define XY_   (NX_ * NY_)     // 129600
#define NCOLB (D_ * W_)       // 10,384 columns per batch (divisible by 8)
#define NCOL  (B_ * NCOLB)    // 41,536 ray columns

// ---------------- kernel 1: zero all of d_out (poisoned 0xAA) --------------
__global__ void zero_out_kernel(float4* __restrict__ o) {
    unsigned i = blockIdx.x * blockDim.x + threadIdx.x;
    o[i] = make_float4(0.f, 0.f, 0.f, 0.f);   // grid sized exactly: no guard
}

// ---------------- kernel 2: warp-per-column scatter, block-wide commit -----
// Structural fact (validated R5-R11): combine[0][1] == combine[1][1] == 0
// exactly in fp32, so gx,gy are identical across the 32 h's of a (b,d,w)
// column; only the cz==0 test varies with h. Phase 1: each of the 8 warps
// computes its column's mask/voxel (lane == h) with ballot + uniformity
// fallback. Phase 2: the proven R7 register-accumulate loop (warp-uniform
// mask -> scalar branch skips failing h's), results staged in smem. Phase 3
// (new): commit CHANNEL-MAJOR across the block's 8 adjacent-w columns —
// 8 consecutive lanes share channel c and hit 8 neighboring q's (cx nearly
// w-invariant, cy within a few cells), collapsing the atomic sector count
// ~4-5x vs per-warp commits 2MB apart.
__global__ void __launch_bounds__(256)
scatter_kernel(const float* __restrict__ x, const float* __restrict__ frustum,
               float* __restrict__ out,
               const float* __restrict__ rots,
               const float* __restrict__ trans,
               const float* __restrict__ intrins) {
    __shared__ float    s_cmb[9];
    __shared__ float    s_tr[3];
    __shared__ float    s_acc[8][C_];
    __shared__ unsigned s_mask[8];
    __shared__ unsigned s_q[8];

    unsigned tid  = threadIdx.x;
    unsigned lane = tid & 31u;                    // lane == h
    unsigned wid  = tid >> 5;
    unsigned col  = blockIdx.x * 8u + wid;        // one column per warp
    unsigned w = col % W_;
    unsigned t = col / W_;
    unsigned d = t % D_;
    unsigned b = t / D_;                          // uniform across the block

    // --- per-block setup: combine = rots[b] @ inv(intrins[b]) (dbl adjugate)
    if (tid == 0) {
        const float* K = intrins + b * 9;
        double a00 = K[0], a01 = K[1], a02 = K[2];
        double a10 = K[3], a11 = K[4], a12 = K[5];
        double a20 = K[6], a21 = K[7], a22 = K[8];
        double det = a00 * (a11 * a22 - a12 * a21)
                   - a01 * (a10 * a22 - a12 * a20)
                   + a02 * (a10 * a21 - a11 * a20);
        double id = 1.0 / det;
        float inv[9];
        inv[0] = (float)(( a11 * a22 - a12 * a21) * id);
        inv[1] = (float)((-(a01 * a22 - a02 * a21)) * id);
        inv[2] = (float)(( a01 * a12 - a02 * a11) * id);
        inv[3] = (float)((-(a10 * a22 - a12 * a20)) * id);
        inv[4] = (float)(( a00 * a22 - a02 * a20) * id);
        inv[5] = (float)((-(a00 * a12 - a02 * a10)) * id);
        inv[6] = (float)(( a10 * a21 - a11 * a20) * id);
        inv[7] = (float)((-(a00 * a21 - a01 * a20)) * id);
        inv[8] = (float)(( a00 * a11 - a01 * a10) * id);
        const float* R = rots + b * 9;
        #pragma unroll
        for (int i = 0; i < 3; i++)
            #pragma unroll
            for (int j = 0; j < 3; j++)
                s_cmb[i * 3 + j] = R[i * 3 + 0] * inv[0 * 3 + j]
                                 + R[i * 3 + 1] * inv[1 * 3 + j]
                                 + R[i * 3 + 2] * inv[2 * 3 + j];
        s_tr[0] = trans[b * 3 + 0];
        s_tr[1] = trans[b * 3 + 1];
        s_tr[2] = trans[b * 3 + 2];
    }
    __syncthreads();

    // --------------- phase 1: mask + voxel for this warp's column -----------
    // frustum (D,H,W,3): [...,0]=u (w only), [...,1]=v (h only), [...,2]=depth
    const float* fr = frustum + ((d * H_ + lane) * W_ + w) * 3u;
    float fu = fr[0];     // uniform across lanes
    float fv = fr[1];     // per-lane (h)
    float fd = fr[2];     // uniform across lanes
    float p0 = fu * fd, p1 = fv * fd, p2 = fd;

    float gx = s_cmb[0] * p0 + s_cmb[1] * p1 + s_cmb[2] * p2 + s_tr[0];
    float gy = s_cmb[3] * p0 + s_cmb[4] * p1 + s_cmb[5] * p2 + s_tr[1];
    float gz = s_cmb[6] * p0 + s_cmb[7] * p1 + s_cmb[8] * p2 + s_tr[2];

    // matches ((geom - BX_LO)/DX).astype(int32): trunc toward zero,
    // incl. the (-1,0)->0 "kept" quirk of the reference
    int cx = (int)((gx + 54.0f) / 0.3f);
    int cy = (int)((gy + 54.0f) / 0.3f);
    int cz = (int)((gz + 10.0f) / 20.0f);

    bool pass = (unsigned)cx < (unsigned)NX_ && (unsigned)cy < (unsigned)NY_
                && cz == 0;
    unsigned mask = __ballot_sync(0xFFFFFFFFu, pass);
    bool live = false;

    unsigned xbase = (((b * D_ + d) * H_) * W_ + w) * (unsigned)C_;   // h = 0

    if (mask != 0u) {
        int src = __ffs(mask) - 1;
        int cx0 = __shfl_sync(0xFFFFFFFFu, cx, src);
        int cy0 = __shfl_sync(0xFFFFFFFFu, cy, src);
        bool uni = __all_sync(0xFFFFFFFFu, !pass || (cx == cx0 && cy == cy0));
        if (uni) {
            live = true;
            if (lane == 0) {
                s_mask[wid] = mask;
                s_q[wid]    = (unsigned)cx0 * NY_ + (unsigned)cy0;
            }
        } else {
            // exact fallback (never expected): per-h scalar scatter now
            if (lane == 0) s_mask[wid] = 0u;
            for (unsigned h = 0; h < H_; h++) {
                if (!((mask >> h) & 1u)) continue;
                int cxh = __shfl_sync(0xFFFFFFFFu, cx, h);
                int cyh = __shfl_sync(0xFFFFFFFFu, cy, h);
                unsigned q = (unsigned)cxh * NY_ + (unsigned)cyh;
                const float* xr = x + xbase + h * (unsigned)(W_ * C_);
                for (unsigned c = lane; c < C_; c += 32)
                    atomicAdd(out + (b * C_ + c) * (unsigned)XY_ + q, xr[c]);
            }
        }
    } else {
        if (lane == 0) s_mask[wid] = 0u;
    }

    // --------------- phase 2: R7 register accumulate -> smem stage ----------
    if (live && lane < C_ / 4) {
        const float* xp = x + xbase + 4u * lane;
        float4 acc = make_float4(0.f, 0.f, 0.f, 0.f);
        #pragma unroll
        for (unsigned h = 0; h < H_; h++) {
            if ((mask >> h) & 1u) {      // warp-uniform: scalar branch
                float4 v = __ldcs(reinterpret_cast<const float4*>(
                    xp + h * (unsigned)(W_ * C_)));
                acc.x += v.x; acc.y += v.y; acc.z += v.z; acc.w += v.w;
            }
        }
        *reinterpret_cast<float4*>(&s_acc[wid][4u * lane]) = acc;
    }
    __syncthreads();

    // --------------- phase 3: channel-major commit across 8 columns ---------
    // idx = tid + k*256 over 640 tasks: cl = idx&7 (column), c = idx>>3.
    // 8 consecutive lanes share c and hit the block's 8 neighboring q's ->
    // 1-2 sectors per channel instead of 8.
    #pragma unroll
    for (int k = 0; k < 3; k++) {
        unsigned idx = tid + k * 256u;
        if (idx >= 8u * C_) break;
        unsigned cl = idx & 7u;
        unsigned c  = idx >> 3;
        if (s_mask[cl] != 0u)
            atomicAdd(out + (b * C_ + c) * (unsigned)XY_ + s_q[cl],
                      s_acc[cl][c]);
    }
}

// ---------------- launch ----------------------------------------------------
extern "C" void kernel_launch(void* const* d_in, const int* in_sizes, int n_in,
                              void* d_out, int out_size) {
    const float* x       = (const float*)d_in[0];
    const float* rots    = (const float*)d_in[1];
    const float* trans   = (const float*)d_in[2];
    const float* intrins = (const float*)d_in[3];
    const float* frustum = (const float*)d_in[4];
    float* out = (float*)d_out;

    // 41,472,000 floats = 10,368,000 float4 = 40500 * 256 exactly
    zero_out_kernel<<<40500, 256>>>(reinterpret_cast<float4*>(out));

    // one warp per (b,d,w) column: 41536 warps, 8 per 256-thread block
    scatter_kernel<<<NCOL / 8, 256>>>(x, frustum, out, rots, trans, intrins);
}